// round 8
// baseline (speedup 1.0000x reference)
#include <cuda_runtime.h>
#include <math.h>

// Problem constants
#define HH     8192
#define IDIM   4096
#define ODIM   4096
#define NTOT   (HH + ODIM)      // 12288
#define NSTEPS 100

// Scratch (no allocations allowed) — 16B aligned for float4 access.
__device__ __align__(128) float g_Ihid[HH];    // compress(W1 @ v_input)
__device__ __align__(128) float g_Iout[ODIM];  // compress(W2 @ I_hidden)
__device__ __align__(128) float g_total[NTOT]; // [I_hidden - Wfb@I_out ; I_out]

__device__ __forceinline__ float compress_fn(float x, float gain) {
    float s = (x > 0.0f) ? 1.0f : ((x < 0.0f) ? -1.0f : 0.0f);
    return s * log1pf(gain * fabsf(x) + 1e-6f);
}

// Block-wide sum reduce for 256 threads (8 warps). Result valid in thread 0.
__device__ __forceinline__ float block_reduce_256(float val) {
    __shared__ float s[8];
    #pragma unroll
    for (int o = 16; o > 0; o >>= 1)
        val += __shfl_xor_sync(0xffffffffu, val, o);
    if ((threadIdx.x & 31) == 0) s[threadIdx.x >> 5] = val;
    __syncthreads();
    if (threadIdx.x < 32) {
        val = (threadIdx.x < 8) ? s[threadIdx.x] : 0.0f;
        #pragma unroll
        for (int o = 4; o > 0; o >>= 1)
            val += __shfl_xor_sync(0xffffffffu, val, o);
    }
    return val;
}

// One block (256 threads) computes dot(W[row, :], x) with float4 loads.
template <int NCOLS>
__device__ __forceinline__ float row_dot(const float* __restrict__ W,
                                         const float* __restrict__ x) {
    const float4* Wr = reinterpret_cast<const float4*>(W) +
                       (size_t)blockIdx.x * (NCOLS / 4);
    const float4* xv = reinterpret_cast<const float4*>(x);
    constexpr int PER = NCOLS / 4 / 256;
    float acc = 0.0f;
    #pragma unroll
    for (int k = 0; k < PER; ++k) {
        int idx = k * 256 + threadIdx.x;
        float4 w = Wr[idx];
        float4 v = xv[idx];
        acc = fmaf(w.x, v.x, acc);
        acc = fmaf(w.y, v.y, acc);
        acc = fmaf(w.z, v.z, acc);
        acc = fmaf(w.w, v.w, acc);
    }
    return acc;
}

// GEMV 1: g_Ihid = compress(W1 @ v_input, gain1)
__global__ __launch_bounds__(256) void k_gemv1(const float* __restrict__ W1,
                                               const float* __restrict__ vin,
                                               const float* __restrict__ gain1) {
    float acc = row_dot<IDIM>(W1, vin);
    acc = block_reduce_256(acc);
    if (threadIdx.x == 0)
        g_Ihid[blockIdx.x] = compress_fn(acc, gain1[0]);
}

// GEMV 2: g_Iout = compress(W2 @ g_Ihid, gain2); also fill g_total[H..]
__global__ __launch_bounds__(256) void k_gemv2(const float* __restrict__ W2,
                                               const float* __restrict__ gain2) {
    float acc = row_dot<HH>(W2, g_Ihid);
    acc = block_reduce_256(acc);
    if (threadIdx.x == 0) {
        float r = compress_fn(acc, gain2[0]);
        g_Iout[blockIdx.x] = r;
        g_total[HH + blockIdx.x] = r;
    }
}

// GEMV 3: g_total[0..H) = g_Ihid - W_feedback @ g_Iout
__global__ __launch_bounds__(256) void k_gemv3(const float* __restrict__ Wfb) {
    float acc = row_dot<ODIM>(Wfb, g_Iout);
    acc = block_reduce_256(acc);
    if (threadIdx.x == 0)
        g_total[blockIdx.x] = g_Ihid[blockIdx.x] - acc;
}

// Izhikevich dynamics: one thread per neuron, 100 steps.
// Output layout: out[0] = loss (written elsewhere),
//   v_vec at out[1 + t*NTOT + i], u_vec at out[1 + NSTEPS*NTOT + t*NTOT + i].
__global__ __launch_bounds__(256) void k_izhi(float* __restrict__ out) {
    int i = blockIdx.x * 256 + threadIdx.x;
    if (i >= NTOT) return;
    float Iin = g_total[i];
    float* vout = out + 1;
    float* uout = out + 1 + (size_t)NSTEPS * NTOT;

    float v = -65.0f;
    float u = 0.2f * -65.0f;   // B * v0 = -13
    vout[i] = v;
    uout[i] = u;

    #pragma unroll 4
    for (int t = 1; t < NSTEPS; ++t) {
        // v_new = v + DT*(0.04 v^2 + 5 v + 0.14 - u + I),  DT = 1
        float vn = v + (0.04f * v * v + 5.0f * v + 0.14f - u + Iin);
        // u_new = u + DT*A*(B*v_prev - u)
        float un = u + 0.02f * (0.2f * v - u);
        bool spiked = (vn >= 30.0f);
        v = spiked ? -65.0f : vn;
        u = spiked ? (un + 8.0f) : un;
        vout[(size_t)t * NTOT + i] = v;
        uout[(size_t)t * NTOT + i] = u;
    }
}

// loss = mean((I_output - target)^2), single block of 1024 threads.
__global__ __launch_bounds__(1024) void k_loss(const float* __restrict__ target,
                                               float* __restrict__ out) {
    float acc = 0.0f;
    for (int i = threadIdx.x; i < ODIM; i += 1024) {
        float d = g_Iout[i] - target[i];
        acc = fmaf(d, d, acc);
    }
    __shared__ float s[32];
    #pragma unroll
    for (int o = 16; o > 0; o >>= 1)
        acc += __shfl_xor_sync(0xffffffffu, acc, o);
    if ((threadIdx.x & 31) == 0) s[threadIdx.x >> 5] = acc;
    __syncthreads();
    if (threadIdx.x < 32) {
        acc = s[threadIdx.x];
        #pragma unroll
        for (int o = 16; o > 0; o >>= 1)
            acc += __shfl_xor_sync(0xffffffffu, acc, o);
        if (threadIdx.x == 0)
            out[0] = acc / (float)ODIM;
    }
}

extern "C" void kernel_launch(void* const* d_in, const int* in_sizes, int n_in,
                              void* d_out, int out_size) {
    // metadata order: v_input, target_output, W1, W2, W_feedback, gain1, gain2
    const float* v_input = (const float*)d_in[0];
    const float* target  = (const float*)d_in[1];
    const float* W1      = (const float*)d_in[2];
    const float* W2      = (const float*)d_in[3];
    const float* Wfb     = (const float*)d_in[4];
    const float* gain1   = (const float*)d_in[5];
    const float* gain2   = (const float*)d_in[6];
    float* out = (float*)d_out;

    k_gemv1<<<HH, 256>>>(W1, v_input, gain1);
    k_gemv2<<<ODIM, 256>>>(W2, gain2);
    k_gemv3<<<HH, 256>>>(Wfb);
    k_izhi<<<(NTOT + 255) / 256, 256>>>(out);
    k_loss<<<1, 1024>>>(target, out);
    (void)in_sizes; (void)n_in; (void)out_size;
}

// round 9
// speedup vs baseline: 1.0031x; 1.0031x over previous
#include <cuda_runtime.h>
#include <math.h>

// Problem constants
#define HH     8192
#define IDIM   4096
#define ODIM   4096
#define NTOT   (HH + ODIM)      // 12288
#define NSTEPS 100

// Scratch (no allocations allowed) — 16B aligned for float4 access.
__device__ __align__(128) float g_Ihid[HH];    // compress(W1 @ v_input)
__device__ __align__(128) float g_Iout[ODIM];  // compress(W2 @ I_hidden)
__device__ __align__(128) float g_total[NTOT]; // [I_hidden - Wfb@I_out ; I_out]

__device__ __forceinline__ float compress_fn(float x, float gain) {
    float s = (x > 0.0f) ? 1.0f : ((x < 0.0f) ? -1.0f : 0.0f);
    return s * log1pf(gain * fabsf(x) + 1e-6f);
}

// Block-wide sum reduce for 256 threads (8 warps). Result valid in thread 0.
__device__ __forceinline__ float block_reduce_256(float val) {
    __shared__ float s[8];
    #pragma unroll
    for (int o = 16; o > 0; o >>= 1)
        val += __shfl_xor_sync(0xffffffffu, val, o);
    if ((threadIdx.x & 31) == 0) s[threadIdx.x >> 5] = val;
    __syncthreads();
    if (threadIdx.x < 32) {
        val = (threadIdx.x < 8) ? s[threadIdx.x] : 0.0f;
        #pragma unroll
        for (int o = 4; o > 0; o >>= 1)
            val += __shfl_xor_sync(0xffffffffu, val, o);
    }
    return val;
}

// One block (256 threads) computes dot(W[row, :], x) with float4 loads.
template <int NCOLS>
__device__ __forceinline__ float row_dot(const float* __restrict__ W,
                                         const float* __restrict__ x) {
    const float4* Wr = reinterpret_cast<const float4*>(W) +
                       (size_t)blockIdx.x * (NCOLS / 4);
    const float4* xv = reinterpret_cast<const float4*>(x);
    constexpr int PER = NCOLS / 4 / 256;
    float acc = 0.0f;
    #pragma unroll
    for (int k = 0; k < PER; ++k) {
        int idx = k * 256 + threadIdx.x;
        float4 w = Wr[idx];
        float4 v = xv[idx];
        acc = fmaf(w.x, v.x, acc);
        acc = fmaf(w.y, v.y, acc);
        acc = fmaf(w.z, v.z, acc);
        acc = fmaf(w.w, v.w, acc);
    }
    return acc;
}

// GEMV 1: g_Ihid = compress(W1 @ v_input, gain1)
__global__ __launch_bounds__(256) void k_gemv1(const float* __restrict__ W1,
                                               const float* __restrict__ vin,
                                               const float* __restrict__ gain1) {
    float acc = row_dot<IDIM>(W1, vin);
    acc = block_reduce_256(acc);
    if (threadIdx.x == 0)
        g_Ihid[blockIdx.x] = compress_fn(acc, gain1[0]);
}

// GEMV 2: g_Iout = compress(W2 @ g_Ihid, gain2); also fill g_total[H..]
__global__ __launch_bounds__(256) void k_gemv2(const float* __restrict__ W2,
                                               const float* __restrict__ gain2) {
    float acc = row_dot<HH>(W2, g_Ihid);
    acc = block_reduce_256(acc);
    if (threadIdx.x == 0) {
        float r = compress_fn(acc, gain2[0]);
        g_Iout[blockIdx.x] = r;
        g_total[HH + blockIdx.x] = r;
    }
}

// GEMV 3: g_total[0..H) = g_Ihid - W_feedback @ g_Iout
__global__ __launch_bounds__(256) void k_gemv3(const float* __restrict__ Wfb) {
    float acc = row_dot<ODIM>(Wfb, g_Iout);
    acc = block_reduce_256(acc);
    if (threadIdx.x == 0)
        g_total[blockIdx.x] = g_Ihid[blockIdx.x] - acc;
}

// Izhikevich dynamics: one thread per neuron, 100 steps.
// Output layout: out[0] = loss (written elsewhere),
//   v_vec at out[1 + t*NTOT + i], u_vec at out[1 + NSTEPS*NTOT + t*NTOT + i].
__global__ __launch_bounds__(256) void k_izhi(float* __restrict__ out) {
    int i = blockIdx.x * 256 + threadIdx.x;
    if (i >= NTOT) return;
    float Iin = g_total[i];
    float* vout = out + 1;
    float* uout = out + 1 + (size_t)NSTEPS * NTOT;

    float v = -65.0f;
    float u = 0.2f * -65.0f;   // B * v0 = -13
    vout[i] = v;
    uout[i] = u;

    #pragma unroll 4
    for (int t = 1; t < NSTEPS; ++t) {
        // v_new = v + DT*(0.04 v^2 + 5 v + 0.14 - u + I),  DT = 1
        float vn = v + (0.04f * v * v + 5.0f * v + 0.14f - u + Iin);
        // u_new = u + DT*A*(B*v_prev - u)
        float un = u + 0.02f * (0.2f * v - u);
        bool spiked = (vn >= 30.0f);
        v = spiked ? -65.0f : vn;
        u = spiked ? (un + 8.0f) : un;
        vout[(size_t)t * NTOT + i] = v;
        uout[(size_t)t * NTOT + i] = u;
    }
}

// loss = mean((I_output - target)^2), single block of 1024 threads.
__global__ __launch_bounds__(1024) void k_loss(const float* __restrict__ target,
                                               float* __restrict__ out) {
    float acc = 0.0f;
    for (int i = threadIdx.x; i < ODIM; i += 1024) {
        float d = g_Iout[i] - target[i];
        acc = fmaf(d, d, acc);
    }
    __shared__ float s[32];
    #pragma unroll
    for (int o = 16; o > 0; o >>= 1)
        acc += __shfl_xor_sync(0xffffffffu, acc, o);
    if ((threadIdx.x & 31) == 0) s[threadIdx.x >> 5] = acc;
    __syncthreads();
    if (threadIdx.x < 32) {
        acc = s[threadIdx.x];
        #pragma unroll
        for (int o = 16; o > 0; o >>= 1)
            acc += __shfl_xor_sync(0xffffffffu, acc, o);
        if (threadIdx.x == 0)
            out[0] = acc / (float)ODIM;
    }
}

extern "C" void kernel_launch(void* const* d_in, const int* in_sizes, int n_in,
                              void* d_out, int out_size) {
    // metadata order: v_input, target_output, W1, W2, W_feedback, gain1, gain2
    const float* v_input = (const float*)d_in[0];
    const float* target  = (const float*)d_in[1];
    const float* W1      = (const float*)d_in[2];
    const float* W2      = (const float*)d_in[3];
    const float* Wfb     = (const float*)d_in[4];
    const float* gain1   = (const float*)d_in[5];
    const float* gain2   = (const float*)d_in[6];
    float* out = (float*)d_out;

    k_gemv1<<<HH, 256>>>(W1, v_input, gain1);
    k_gemv2<<<ODIM, 256>>>(W2, gain2);
    k_gemv3<<<HH, 256>>>(Wfb);
    k_izhi<<<(NTOT + 255) / 256, 256>>>(out);
    k_loss<<<1, 1024>>>(target, out);
    (void)in_sizes; (void)n_in; (void)out_size;
}